// round 1
// baseline (speedup 1.0000x reference)
#include <cuda_runtime.h>
#include <math.h>

// Problem constants
#define B_SZ   2
#define L_SZ   2048
#define D_SZ   1024
#define H_SZ   16
#define DH     64
#define M_SZ   (B_SZ * L_SZ)   // 4096

// Scratch (device globals: no allocation allowed in kernel_launch)
__device__ float g_qp[M_SZ * D_SZ];
__device__ float g_kp[M_SZ * D_SZ];
__device__ float g_vp[M_SZ * D_SZ];
__device__ float g_ctx[M_SZ * D_SZ];

// ======================================================================
// GEMM (NT): C[m][n] = sum_k A[m][k] * W[n][k] + bias[n]
// A: [Mdim, Kdim] row-major, W: [Ndim, Kdim] row-major (torch Linear weight)
// 128x128 block tile, K-slice 8, 256 threads, 8x8 register microtile.
// ======================================================================
#define GBM 128
#define GBN 128
#define GBK 8

__global__ __launch_bounds__(256, 2)
void gemm_nt_kernel(const float* __restrict__ A, const float* __restrict__ W,
                    const float* __restrict__ bias, float* __restrict__ C,
                    int Mdim, int Ndim, int Kdim)
{
    __shared__ float As[GBK][GBM + 4];
    __shared__ float Bs[GBK][GBN + 4];

    const int tid = threadIdx.x;
    const int tx  = tid & 15;     // 0..15 -> n microtile
    const int ty  = tid >> 4;     // 0..15 -> m microtile
    const int m0  = blockIdx.y * GBM;
    const int n0  = blockIdx.x * GBN;

    // Loader mapping: 128x8 tile = 1024 floats = 256 threads * float4
    const int lrow = tid >> 1;          // 0..127
    const int lcol = (tid & 1) * 4;     // 0 or 4

    const float* Ag = A + (size_t)(m0 + lrow) * Kdim + lcol;
    const float* Bg = W + (size_t)(n0 + lrow) * Kdim + lcol;

    float acc[8][8];
#pragma unroll
    for (int i = 0; i < 8; i++)
#pragma unroll
        for (int j = 0; j < 8; j++) acc[i][j] = 0.0f;

    float4 aReg = *(const float4*)Ag;
    float4 bReg = *(const float4*)Bg;

    for (int k0 = 0; k0 < Kdim; k0 += GBK) {
        As[lcol + 0][lrow] = aReg.x;
        As[lcol + 1][lrow] = aReg.y;
        As[lcol + 2][lrow] = aReg.z;
        As[lcol + 3][lrow] = aReg.w;
        Bs[lcol + 0][lrow] = bReg.x;
        Bs[lcol + 1][lrow] = bReg.y;
        Bs[lcol + 2][lrow] = bReg.z;
        Bs[lcol + 3][lrow] = bReg.w;
        __syncthreads();

        if (k0 + GBK < Kdim) {
            aReg = *(const float4*)(Ag + k0 + GBK);
            bReg = *(const float4*)(Bg + k0 + GBK);
        }

#pragma unroll
        for (int kk = 0; kk < GBK; kk++) {
            float a[8], b[8];
            *(float4*)&a[0] = *(const float4*)&As[kk][ty * 8];
            *(float4*)&a[4] = *(const float4*)&As[kk][ty * 8 + 4];
            *(float4*)&b[0] = *(const float4*)&Bs[kk][tx * 8];
            *(float4*)&b[4] = *(const float4*)&Bs[kk][tx * 8 + 4];
#pragma unroll
            for (int i = 0; i < 8; i++)
#pragma unroll
                for (int j = 0; j < 8; j++)
                    acc[i][j] = fmaf(a[i], b[j], acc[i][j]);
        }
        __syncthreads();
    }

    // Epilogue: add bias, vectorized stores
    float bvec[8];
#pragma unroll
    for (int j = 0; j < 8; j++) bvec[j] = bias[n0 + tx * 8 + j];

#pragma unroll
    for (int i = 0; i < 8; i++) {
        int m = m0 + ty * 8 + i;
        float* Crow = C + (size_t)m * Ndim + n0 + tx * 8;
        float4 v0, v1;
        v0.x = acc[i][0] + bvec[0]; v0.y = acc[i][1] + bvec[1];
        v0.z = acc[i][2] + bvec[2]; v0.w = acc[i][3] + bvec[3];
        v1.x = acc[i][4] + bvec[4]; v1.y = acc[i][5] + bvec[5];
        v1.z = acc[i][6] + bvec[6]; v1.w = acc[i][7] + bvec[7];
        *(float4*)&Crow[0] = v0;
        *(float4*)&Crow[4] = v1;
    }
}

// ======================================================================
// Flash attention (fp32, online softmax).
// Grid: (B*H, L/BQ). Block: 128 threads.
// Per block: 64 query rows of one head; stream 64-key tiles of K/V.
// Shared layouts (d-major transposed for Q,K so fragment reads are
// conflict-free; stride 65 kills row-broadcast bank conflicts):
//   Qst[d][i]  stride 65
//   Kst[d][j]  stride 65
//   Vs [j][d]  stride 64
//   Ss [i][j]  stride 65
// Thread (tx=tid&7, ty=tid>>3): rows i = ty + 16*ii (ii<4),
// cols (j or d) = tx + 8*jj (jj<8). 32 accumulators per thread.
// ======================================================================
#define BQ  64
#define BKT 64
#define QK_STRIDE 65
#define ATT_SMEM_FLOATS (3 * 64 * QK_STRIDE + 64 * 64 + 3 * 64)
#define ATT_SMEM_BYTES  (ATT_SMEM_FLOATS * 4)

__global__ __launch_bounds__(128)
void attn_kernel(const float* __restrict__ qp, const float* __restrict__ kp,
                 const float* __restrict__ vp, float* __restrict__ ctx)
{
    extern __shared__ float sm[];
    float* Qst   = sm;                       // 64*65
    float* Kst   = Qst + 64 * QK_STRIDE;     // 64*65
    float* Ss    = Kst + 64 * QK_STRIDE;     // 64*65
    float* Vs    = Ss  + 64 * QK_STRIDE;     // 64*64
    float* row_m = Vs  + 64 * 64;            // 64
    float* row_l = row_m + 64;               // 64
    float* row_sc= row_l + 64;               // 64

    const int tid = threadIdx.x;
    const int tx  = tid & 7;
    const int ty  = tid >> 3;

    const int bh = blockIdx.x;
    const int b  = bh >> 4;          // bh / H
    const int h  = bh & 15;          // bh % H
    const int q0 = blockIdx.y * BQ;

    const size_t head_off = (size_t)h * DH;

    // Load Q tile transposed: Qst[d][i]
    {
        const int i_base = tid >> 4;      // 0..7
        const int d4     = tid & 15;      // 0..15 -> d = d4*4
#pragma unroll
        for (int s = 0; s < 8; s++) {
            int i = i_base + s * 8;
            float4 v = *(const float4*)&qp[((size_t)(b * L_SZ + q0 + i)) * D_SZ + head_off + d4 * 4];
            Qst[(d4 * 4 + 0) * QK_STRIDE + i] = v.x;
            Qst[(d4 * 4 + 1) * QK_STRIDE + i] = v.y;
            Qst[(d4 * 4 + 2) * QK_STRIDE + i] = v.z;
            Qst[(d4 * 4 + 3) * QK_STRIDE + i] = v.w;
        }
    }
    if (tid < 64) {
        row_m[tid] = -INFINITY;
        row_l[tid] = 0.0f;
    }

    float o_acc[4][8];
#pragma unroll
    for (int ii = 0; ii < 4; ii++)
#pragma unroll
        for (int jj = 0; jj < 8; jj++) o_acc[ii][jj] = 0.0f;

    const float scale = 0.125f;   // 1/sqrt(64)

    for (int kt = 0; kt < L_SZ / BKT; kt++) {
        const int k0 = kt * BKT;

        // Load K tile transposed + V tile natural
        {
            const int r_base = tid >> 4;
            const int d4     = tid & 15;
#pragma unroll
            for (int s = 0; s < 8; s++) {
                int j = r_base + s * 8;
                float4 v = *(const float4*)&kp[((size_t)(b * L_SZ + k0 + j)) * D_SZ + head_off + d4 * 4];
                Kst[(d4 * 4 + 0) * QK_STRIDE + j] = v.x;
                Kst[(d4 * 4 + 1) * QK_STRIDE + j] = v.y;
                Kst[(d4 * 4 + 2) * QK_STRIDE + j] = v.z;
                Kst[(d4 * 4 + 3) * QK_STRIDE + j] = v.w;
                float4 w = *(const float4*)&vp[((size_t)(b * L_SZ + k0 + j)) * D_SZ + head_off + d4 * 4];
                *(float4*)&Vs[j * 64 + d4 * 4] = w;
            }
        }
        __syncthreads();

        // S = (Q @ K^T) * scale  -> Ss
        {
            float s_acc[4][8];
#pragma unroll
            for (int ii = 0; ii < 4; ii++)
#pragma unroll
                for (int jj = 0; jj < 8; jj++) s_acc[ii][jj] = 0.0f;

#pragma unroll 4
            for (int d = 0; d < DH; d++) {
                float af[4], bf[8];
#pragma unroll
                for (int ii = 0; ii < 4; ii++) af[ii] = Qst[d * QK_STRIDE + ty + 16 * ii];
#pragma unroll
                for (int jj = 0; jj < 8; jj++) bf[jj] = Kst[d * QK_STRIDE + tx + 8 * jj];
#pragma unroll
                for (int ii = 0; ii < 4; ii++)
#pragma unroll
                    for (int jj = 0; jj < 8; jj++)
                        s_acc[ii][jj] = fmaf(af[ii], bf[jj], s_acc[ii][jj]);
            }
#pragma unroll
            for (int ii = 0; ii < 4; ii++)
#pragma unroll
                for (int jj = 0; jj < 8; jj++)
                    Ss[(ty + 16 * ii) * QK_STRIDE + tx + 8 * jj] = s_acc[ii][jj] * scale;
        }
        __syncthreads();

        // Online softmax per row (64 rows, threads 0..63)
        if (tid < 64) {
            const int r = tid;
            float m_old = row_m[r];
            float mx = m_old;
#pragma unroll 8
            for (int j = 0; j < BKT; j++) mx = fmaxf(mx, Ss[r * QK_STRIDE + j]);
            float sum = 0.0f;
#pragma unroll 8
            for (int j = 0; j < BKT; j++) {
                float e = __expf(Ss[r * QK_STRIDE + j] - mx);
                Ss[r * QK_STRIDE + j] = e;
                sum += e;
            }
            float sc = __expf(m_old - mx);   // expf(-inf)=0 on first tile
            row_l[r] = row_l[r] * sc + sum;
            row_m[r] = mx;
            row_sc[r] = sc;
        }
        __syncthreads();

        // O = O*sc + P @ V
        {
#pragma unroll
            for (int ii = 0; ii < 4; ii++) {
                float sc = row_sc[ty + 16 * ii];
#pragma unroll
                for (int jj = 0; jj < 8; jj++) o_acc[ii][jj] *= sc;
            }
#pragma unroll 4
            for (int j = 0; j < BKT; j++) {
                float pf[4], vf[8];
#pragma unroll
                for (int ii = 0; ii < 4; ii++) pf[ii] = Ss[(ty + 16 * ii) * QK_STRIDE + j];
#pragma unroll
                for (int jj = 0; jj < 8; jj++) vf[jj] = Vs[j * 64 + tx + 8 * jj];
#pragma unroll
                for (int ii = 0; ii < 4; ii++)
#pragma unroll
                    for (int jj = 0; jj < 8; jj++)
                        o_acc[ii][jj] = fmaf(pf[ii], vf[jj], o_acc[ii][jj]);
            }
        }
        __syncthreads();   // before overwriting Kst/Vs/Ss next tile
    }

    // Normalize and write ctx[b, q0+i, h, d]
#pragma unroll
    for (int ii = 0; ii < 4; ii++) {
        int i = ty + 16 * ii;
        float inv = 1.0f / row_l[i];
        float* orow = ctx + ((size_t)(b * L_SZ + q0 + i)) * D_SZ + head_off;
#pragma unroll
        for (int jj = 0; jj < 8; jj++)
            orow[tx + 8 * jj] = o_acc[ii][jj] * inv;
    }
}

// ======================================================================
// Launch
// ======================================================================
extern "C" void kernel_launch(void* const* d_in, const int* in_sizes, int n_in,
                              void* d_out, int out_size)
{
    const float* q   = (const float*)d_in[0];
    const float* k   = (const float*)d_in[1];
    const float* v   = (const float*)d_in[2];
    const float* w_q = (const float*)d_in[3];
    const float* b_q = (const float*)d_in[4];
    const float* w_k = (const float*)d_in[5];
    const float* b_k = (const float*)d_in[6];
    const float* w_v = (const float*)d_in[7];
    const float* b_v = (const float*)d_in[8];
    const float* w_o = (const float*)d_in[9];
    const float* b_o = (const float*)d_in[10];
    float* out = (float*)d_out;

    float *qp, *kp, *vp, *ctx;
    cudaGetSymbolAddress((void**)&qp,  g_qp);
    cudaGetSymbolAddress((void**)&kp,  g_kp);
    cudaGetSymbolAddress((void**)&vp,  g_vp);
    cudaGetSymbolAddress((void**)&ctx, g_ctx);

    cudaFuncSetAttribute(attn_kernel,
                         cudaFuncAttributeMaxDynamicSharedMemorySize,
                         ATT_SMEM_BYTES);

    dim3 gThreads(256);
    dim3 gGrid(D_SZ / GBN, M_SZ / GBM);   // (8, 32)

    gemm_nt_kernel<<<gGrid, gThreads>>>(q, w_q, b_q, qp, M_SZ, D_SZ, D_SZ);
    gemm_nt_kernel<<<gGrid, gThreads>>>(k, w_k, b_k, kp, M_SZ, D_SZ, D_SZ);
    gemm_nt_kernel<<<gGrid, gThreads>>>(v, w_v, b_v, vp, M_SZ, D_SZ, D_SZ);

    dim3 aGrid(B_SZ * H_SZ, L_SZ / BQ);   // (32, 32)
    attn_kernel<<<aGrid, 128, ATT_SMEM_BYTES>>>(qp, kp, vp, ctx);

    gemm_nt_kernel<<<gGrid, gThreads>>>(ctx, w_o, b_o, out, M_SZ, D_SZ, D_SZ);
}

// round 2
// speedup vs baseline: 1.7031x; 1.7031x over previous
#include <cuda_runtime.h>
#include <math.h>

// Problem constants
#define B_SZ   2
#define L_SZ   2048
#define D_SZ   1024
#define H_SZ   16
#define DH     64
#define M_SZ   (B_SZ * L_SZ)   // 4096

// Scratch (device globals; no allocation allowed in kernel_launch)
__device__ float g_qp[M_SZ * D_SZ];
__device__ float g_kp[M_SZ * D_SZ];
__device__ float g_vp[M_SZ * D_SZ];
__device__ float g_ctx[M_SZ * D_SZ];

// ---------------------------------------------------------------------
// tf32 helpers
// ---------------------------------------------------------------------
__device__ __forceinline__ unsigned f2tf(float x) {
    unsigned u;
    asm("cvt.rna.tf32.f32 %0, %1;" : "=r"(u) : "f"(x));
    return u;
}

// D = A(16x8) * B(8x8) + D, tf32 inputs, fp32 accum
__device__ __forceinline__ void mma8(float* c, const unsigned* a, const unsigned* b) {
    asm volatile(
        "mma.sync.aligned.m16n8k8.row.col.f32.tf32.tf32.f32 "
        "{%0,%1,%2,%3}, {%4,%5,%6,%7}, {%8,%9}, {%0,%1,%2,%3};"
        : "+f"(c[0]), "+f"(c[1]), "+f"(c[2]), "+f"(c[3])
        : "r"(a[0]), "r"(a[1]), "r"(a[2]), "r"(a[3]), "r"(b[0]), "r"(b[1]));
}

// ======================================================================
// GEMM (NT): C[m][n] = sum_k A[m][k] * W[n][k] + bias[n]   (tf32 mma)
// 128x128 block tile, BK=16, 256 threads (8 warps, 2x4), warp tile 64x32.
// smem row stride 20 -> conflict-free fragment LDS for the
// (row = lane>>2, col = lane&3) pattern: bank = (20r + c) % 32 = (4r+c)%32,
// all 32 distinct over r in 0..7, c in 0..3.
// ======================================================================
#define GM 128
#define GN 128
#define GK 16
#define GSTR 20

__global__ __launch_bounds__(256, 2)
void gemm_tf32(const float* __restrict__ A, const float* __restrict__ W,
               const float* __restrict__ bias, float* __restrict__ C,
               int Mdim, int Ndim, int Kdim)
{
    __shared__ unsigned As[GM * GSTR];
    __shared__ unsigned Ws[GN * GSTR];

    const int tid  = threadIdx.x;
    const int lane = tid & 31;
    const int warp = tid >> 5;
    const int wm   = (warp >> 2) * 64;   // 0 or 64
    const int wn   = (warp & 3) * 32;    // 0,32,64,96
    const int g    = lane >> 2;          // 0..7
    const int tg   = lane & 3;           // 0..3

    const int m0 = blockIdx.y * GM;
    const int n0 = blockIdx.x * GN;

    // loader: row = tid>>2 (0..63, +64 second pass), cols (tid&3)*4 .. +3
    const int lrow = tid >> 2;
    const int lcol = (tid & 3) * 4;

    const float* Ag = A + (size_t)(m0 + lrow) * Kdim + lcol;
    const float* Wg = W + (size_t)(n0 + lrow) * Kdim + lcol;
    const size_t rstep = (size_t)64 * Kdim;

    float c[4][4][4];
#pragma unroll
    for (int i = 0; i < 4; i++)
#pragma unroll
        for (int j = 0; j < 4; j++)
#pragma unroll
            for (int e = 0; e < 4; e++) c[i][j][e] = 0.0f;

    float4 aR0 = *(const float4*)(Ag);
    float4 aR1 = *(const float4*)(Ag + rstep);
    float4 wR0 = *(const float4*)(Wg);
    float4 wR1 = *(const float4*)(Wg + rstep);

    for (int k0 = 0; k0 < Kdim; k0 += GK) {
        {
            unsigned* p = &As[lrow * GSTR + lcol];
            p[0] = f2tf(aR0.x); p[1] = f2tf(aR0.y); p[2] = f2tf(aR0.z); p[3] = f2tf(aR0.w);
            p += 64 * GSTR;
            p[0] = f2tf(aR1.x); p[1] = f2tf(aR1.y); p[2] = f2tf(aR1.z); p[3] = f2tf(aR1.w);
            unsigned* q = &Ws[lrow * GSTR + lcol];
            q[0] = f2tf(wR0.x); q[1] = f2tf(wR0.y); q[2] = f2tf(wR0.z); q[3] = f2tf(wR0.w);
            q += 64 * GSTR;
            q[0] = f2tf(wR1.x); q[1] = f2tf(wR1.y); q[2] = f2tf(wR1.z); q[3] = f2tf(wR1.w);
        }
        __syncthreads();

        if (k0 + GK < Kdim) {
            aR0 = *(const float4*)(Ag + k0 + GK);
            aR1 = *(const float4*)(Ag + k0 + GK + rstep);
            wR0 = *(const float4*)(Wg + k0 + GK);
            wR1 = *(const float4*)(Wg + k0 + GK + rstep);
        }

#pragma unroll
        for (int kk = 0; kk < 2; kk++) {
            const int kc = kk * 8 + tg;
            unsigned a[4][4], b[4][2];
#pragma unroll
            for (int ma = 0; ma < 4; ma++) {
                const int r = wm + ma * 16 + g;
                a[ma][0] = As[r * GSTR + kc];
                a[ma][1] = As[(r + 8) * GSTR + kc];
                a[ma][2] = As[r * GSTR + kc + 4];
                a[ma][3] = As[(r + 8) * GSTR + kc + 4];
            }
#pragma unroll
            for (int na = 0; na < 4; na++) {
                const int n = wn + na * 8 + g;
                b[na][0] = Ws[n * GSTR + kc];
                b[na][1] = Ws[n * GSTR + kc + 4];
            }
#pragma unroll
            for (int ma = 0; ma < 4; ma++)
#pragma unroll
                for (int na = 0; na < 4; na++)
                    mma8(c[ma][na], a[ma], b[na]);
        }
        __syncthreads();
    }

    // epilogue
#pragma unroll
    for (int ma = 0; ma < 4; ma++) {
        const int r = m0 + wm + ma * 16 + g;
#pragma unroll
        for (int na = 0; na < 4; na++) {
            const int cc = n0 + wn + na * 8 + 2 * tg;
            const float b0 = bias[cc], b1 = bias[cc + 1];
            float2 u0 = make_float2(c[ma][na][0] + b0, c[ma][na][1] + b1);
            float2 u1 = make_float2(c[ma][na][2] + b0, c[ma][na][3] + b1);
            *(float2*)&C[(size_t)r * Ndim + cc]       = u0;
            *(float2*)&C[(size_t)(r + 8) * Ndim + cc] = u1;
        }
    }
}

// ======================================================================
// Flash attention, tf32 mma, online softmax with register-resident stats.
// Grid (B*H, L/64), 128 threads (4 warps), each warp owns 16 q-rows.
// smem: K[64][68], V[64][72], Q[64][68] (aliased as S/P after Q frags
// are hoisted). All fragment LDS patterns conflict-free by stride choice.
// Softmax reductions via shuffles over the 4-lane row groups of the
// mma C-fragment; S/P smem traffic is warp-private (syncwarp only).
// ======================================================================
#define QSTR 68
#define VSTR 72
#define ATT_SMEM_BYTES ((64 * QSTR + 64 * VSTR + 64 * QSTR) * 4)

__global__ __launch_bounds__(128)
void attn_tf32(const float* __restrict__ qp, const float* __restrict__ kp,
               const float* __restrict__ vp, float* __restrict__ ctx)
{
    extern __shared__ unsigned smu[];
    unsigned* Ks = smu;
    unsigned* Vs = Ks + 64 * QSTR;
    unsigned* Qs = Vs + 64 * VSTR;   // also used as Ss (P tile) after hoist
    unsigned* Ss = Qs;

    const int tid  = threadIdx.x;
    const int lane = tid & 31;
    const int warp = tid >> 5;
    const int g    = lane >> 2;
    const int tg   = lane & 3;

    const int bh = blockIdx.x;
    const int b  = bh >> 4;
    const int h  = bh & 15;
    const int q0 = blockIdx.y * 64;
    const int head = h * DH;

    // ---- load Q tile, pre-scaled by 1/sqrt(64), tf32-rounded ----
    const int lr  = tid >> 1;           // 0..63
    const int lc0 = (tid & 1) * 4;
    {
        const float* qg = qp + (size_t)(b * L_SZ + q0 + lr) * D_SZ + head;
#pragma unroll
        for (int c8 = 0; c8 < 8; c8++) {
            float4 v = *(const float4*)(qg + lc0 + c8 * 8);
            unsigned* dst = &Qs[lr * QSTR + lc0 + c8 * 8];
            dst[0] = f2tf(v.x * 0.125f);
            dst[1] = f2tf(v.y * 0.125f);
            dst[2] = f2tf(v.z * 0.125f);
            dst[3] = f2tf(v.w * 0.125f);
        }
    }
    __syncthreads();

    // ---- hoist Q fragments (warp-local rows) ----
    const int r1 = warp * 16 + g;       // this thread's primary row
    unsigned qf[8][4];
#pragma unroll
    for (int ks = 0; ks < 8; ks++) {
        const int kc = ks * 8 + tg;
        qf[ks][0] = Qs[r1 * QSTR + kc];
        qf[ks][1] = Qs[(r1 + 8) * QSTR + kc];
        qf[ks][2] = Qs[r1 * QSTR + kc + 4];
        qf[ks][3] = Qs[(r1 + 8) * QSTR + kc + 4];
    }

    float of[8][4];
#pragma unroll
    for (int na = 0; na < 8; na++)
#pragma unroll
        for (int e = 0; e < 4; e++) of[na][e] = 0.0f;

    float m1 = -INFINITY, m2 = -INFINITY, l1 = 0.0f, l2 = 0.0f;

    const float* kg = kp + (size_t)(b * L_SZ + lr) * D_SZ + head;
    const float* vg = vp + (size_t)(b * L_SZ + lr) * D_SZ + head;

    for (int kt = 0; kt < L_SZ / 64; kt++) {
        __syncthreads();   // previous tile's LDS of Ks/Vs complete

        // ---- load K/V tile (rows kt*64 + lr) ----
        {
            const float* kgp = kg + (size_t)kt * 64 * D_SZ;
            const float* vgp = vg + (size_t)kt * 64 * D_SZ;
#pragma unroll
            for (int c8 = 0; c8 < 8; c8++) {
                float4 kv = *(const float4*)(kgp + lc0 + c8 * 8);
                unsigned* kd = &Ks[lr * QSTR + lc0 + c8 * 8];
                kd[0] = f2tf(kv.x); kd[1] = f2tf(kv.y);
                kd[2] = f2tf(kv.z); kd[3] = f2tf(kv.w);
                float4 vv = *(const float4*)(vgp + lc0 + c8 * 8);
                unsigned* vd = &Vs[lr * VSTR + lc0 + c8 * 8];
                vd[0] = f2tf(vv.x); vd[1] = f2tf(vv.y);
                vd[2] = f2tf(vv.z); vd[3] = f2tf(vv.w);
            }
        }
        __syncthreads();

        // ---- S = (Q/8) @ K^T ----
        float sf[8][4];
#pragma unroll
        for (int na = 0; na < 8; na++)
#pragma unroll
            for (int e = 0; e < 4; e++) sf[na][e] = 0.0f;

#pragma unroll
        for (int ks = 0; ks < 8; ks++) {
            const int kc = ks * 8 + tg;
            unsigned bf[8][2];
#pragma unroll
            for (int na = 0; na < 8; na++) {
                const int n = na * 8 + g;
                bf[na][0] = Ks[n * QSTR + kc];
                bf[na][1] = Ks[n * QSTR + kc + 4];
            }
#pragma unroll
            for (int na = 0; na < 8; na++)
                mma8(sf[na], qf[ks], bf[na]);
        }

        // ---- online softmax (register stats, shuffle row-reduce) ----
        float mx1 = -INFINITY, mx2 = -INFINITY;
#pragma unroll
        for (int na = 0; na < 8; na++) {
            mx1 = fmaxf(mx1, fmaxf(sf[na][0], sf[na][1]));
            mx2 = fmaxf(mx2, fmaxf(sf[na][2], sf[na][3]));
        }
        mx1 = fmaxf(mx1, __shfl_xor_sync(0xffffffffu, mx1, 1));
        mx1 = fmaxf(mx1, __shfl_xor_sync(0xffffffffu, mx1, 2));
        mx2 = fmaxf(mx2, __shfl_xor_sync(0xffffffffu, mx2, 1));
        mx2 = fmaxf(mx2, __shfl_xor_sync(0xffffffffu, mx2, 2));

        const float mn1 = fmaxf(m1, mx1);
        const float mn2 = fmaxf(m2, mx2);
        const float fa1 = __expf(m1 - mn1);   // 0 on first tile
        const float fa2 = __expf(m2 - mn2);

        float s1 = 0.0f, s2 = 0.0f;
#pragma unroll
        for (int na = 0; na < 8; na++) {
            const float e0 = __expf(sf[na][0] - mn1);
            const float e1 = __expf(sf[na][1] - mn1);
            const float e2 = __expf(sf[na][2] - mn2);
            const float e3 = __expf(sf[na][3] - mn2);
            s1 += e0 + e1;
            s2 += e2 + e3;
            const int cc = na * 8 + 2 * tg;
            Ss[r1 * QSTR + cc]           = f2tf(e0);
            Ss[r1 * QSTR + cc + 1]       = f2tf(e1);
            Ss[(r1 + 8) * QSTR + cc]     = f2tf(e2);
            Ss[(r1 + 8) * QSTR + cc + 1] = f2tf(e3);
        }
        s1 += __shfl_xor_sync(0xffffffffu, s1, 1);
        s1 += __shfl_xor_sync(0xffffffffu, s1, 2);
        s2 += __shfl_xor_sync(0xffffffffu, s2, 1);
        s2 += __shfl_xor_sync(0xffffffffu, s2, 2);

        l1 = l1 * fa1 + s1;  m1 = mn1;
        l2 = l2 * fa2 + s2;  m2 = mn2;

#pragma unroll
        for (int na = 0; na < 8; na++) {
            of[na][0] *= fa1; of[na][1] *= fa1;
            of[na][2] *= fa2; of[na][3] *= fa2;
        }
        __syncwarp();   // Ss is warp-private: rows r1..r1+15 all owned here

        // ---- O += P @ V ----
#pragma unroll
        for (int ks = 0; ks < 8; ks++) {
            const int kc = ks * 8 + tg;
            unsigned pa[4];
            pa[0] = Ss[r1 * QSTR + kc];
            pa[1] = Ss[(r1 + 8) * QSTR + kc];
            pa[2] = Ss[r1 * QSTR + kc + 4];
            pa[3] = Ss[(r1 + 8) * QSTR + kc + 4];
            unsigned vb[8][2];
#pragma unroll
            for (int na = 0; na < 8; na++) {
                const int n = na * 8 + g;
                vb[na][0] = Vs[(ks * 8 + tg) * VSTR + n];
                vb[na][1] = Vs[(ks * 8 + tg + 4) * VSTR + n];
            }
#pragma unroll
            for (int na = 0; na < 8; na++)
                mma8(of[na], pa, vb[na]);
        }
    }

    // ---- normalize + write ----
    const float inv1 = 1.0f / l1;
    const float inv2 = 1.0f / l2;
    float* o1 = ctx + (size_t)(b * L_SZ + q0 + r1) * D_SZ + head;
    float* o2 = ctx + (size_t)(b * L_SZ + q0 + r1 + 8) * D_SZ + head;
#pragma unroll
    for (int na = 0; na < 8; na++) {
        const int cc = na * 8 + 2 * tg;
        *(float2*)(o1 + cc) = make_float2(of[na][0] * inv1, of[na][1] * inv1);
        *(float2*)(o2 + cc) = make_float2(of[na][2] * inv2, of[na][3] * inv2);
    }
}

// ======================================================================
// Launch
// ======================================================================
extern "C" void kernel_launch(void* const* d_in, const int* in_sizes, int n_in,
                              void* d_out, int out_size)
{
    const float* q   = (const float*)d_in[0];
    const float* k   = (const float*)d_in[1];
    const float* v   = (const float*)d_in[2];
    const float* w_q = (const float*)d_in[3];
    const float* b_q = (const float*)d_in[4];
    const float* w_k = (const float*)d_in[5];
    const float* b_k = (const float*)d_in[6];
    const float* w_v = (const float*)d_in[7];
    const float* b_v = (const float*)d_in[8];
    const float* w_o = (const float*)d_in[9];
    const float* b_o = (const float*)d_in[10];
    float* out = (float*)d_out;

    float *qp, *kp, *vp, *ctx;
    cudaGetSymbolAddress((void**)&qp,  g_qp);
    cudaGetSymbolAddress((void**)&kp,  g_kp);
    cudaGetSymbolAddress((void**)&vp,  g_vp);
    cudaGetSymbolAddress((void**)&ctx, g_ctx);

    cudaFuncSetAttribute(attn_tf32,
                         cudaFuncAttributeMaxDynamicSharedMemorySize,
                         ATT_SMEM_BYTES);

    dim3 gThreads(256);
    dim3 gGrid(D_SZ / GN, M_SZ / GM);   // (8, 32)

    gemm_tf32<<<gGrid, gThreads>>>(q, w_q, b_q, qp, M_SZ, D_SZ, D_SZ);
    gemm_tf32<<<gGrid, gThreads>>>(k, w_k, b_k, kp, M_SZ, D_SZ, D_SZ);
    gemm_tf32<<<gGrid, gThreads>>>(v, w_v, b_v, vp, M_SZ, D_SZ, D_SZ);

    dim3 aGrid(B_SZ * H_SZ, L_SZ / 64);  // (32, 32)
    attn_tf32<<<aGrid, 128, ATT_SMEM_BYTES>>>(qp, kp, vp, ctx);

    gemm_tf32<<<gGrid, gThreads>>>(ctx, w_o, b_o, out, M_SZ, D_SZ, D_SZ);
}

// round 4
// speedup vs baseline: 5.2786x; 3.0995x over previous
#include <cuda_runtime.h>
#include <cuda_fp16.h>
#include <math.h>

#define B_SZ   2
#define L_SZ   2048
#define D_SZ   1024
#define H_SZ   16
#define DH     64
#define M_SZ   (B_SZ * L_SZ)   // 4096

// ---------------- scratch (device globals) ----------------
__device__ __half g_qh[M_SZ * D_SZ];
__device__ __half g_kh[M_SZ * D_SZ];
__device__ __half g_vh[M_SZ * D_SZ];
__device__ __half g_wqh[D_SZ * D_SZ];
__device__ __half g_wkh[D_SZ * D_SZ];
__device__ __half g_wvh[D_SZ * D_SZ];
__device__ __half g_woh[D_SZ * D_SZ];
__device__ __half g_qp[M_SZ * D_SZ];
__device__ __half g_kp[M_SZ * D_SZ];
__device__ __half g_vp[M_SZ * D_SZ];
__device__ __half g_ctx[M_SZ * D_SZ];

// ---------------- PTX helpers ----------------
__device__ __forceinline__ unsigned sptr(const void* p) {
    return (unsigned)__cvta_generic_to_shared(p);
}
__device__ __forceinline__ void ldsm4(unsigned& a, unsigned& b, unsigned& c, unsigned& d,
                                      unsigned addr) {
    asm volatile("ldmatrix.sync.aligned.m8n8.x4.shared.b16 {%0,%1,%2,%3}, [%4];"
                 : "=r"(a), "=r"(b), "=r"(c), "=r"(d) : "r"(addr));
}
__device__ __forceinline__ void ldsm4t(unsigned& a, unsigned& b, unsigned& c, unsigned& d,
                                       unsigned addr) {
    asm volatile("ldmatrix.sync.aligned.m8n8.x4.trans.shared.b16 {%0,%1,%2,%3}, [%4];"
                 : "=r"(a), "=r"(b), "=r"(c), "=r"(d) : "r"(addr));
}
__device__ __forceinline__ void mma16(float* c, const unsigned* a, unsigned b0, unsigned b1) {
    asm volatile(
        "mma.sync.aligned.m16n8k16.row.col.f32.f16.f16.f32 "
        "{%0,%1,%2,%3}, {%4,%5,%6,%7}, {%8,%9}, {%0,%1,%2,%3};"
        : "+f"(c[0]), "+f"(c[1]), "+f"(c[2]), "+f"(c[3])
        : "r"(a[0]), "r"(a[1]), "r"(a[2]), "r"(a[3]), "r"(b0), "r"(b1));
}
__device__ __forceinline__ void cp16(unsigned s, const void* g) {
    asm volatile("cp.async.cg.shared.global [%0], [%1], 16;" :: "r"(s), "l"(g));
}
#define CP_COMMIT asm volatile("cp.async.commit_group;")
#define CP_WAIT1  asm volatile("cp.async.wait_group 1;")
#define CP_WAIT0  asm volatile("cp.async.wait_group 0;")

__device__ __forceinline__ unsigned pack_h2(float a, float b) {
    __half2 h = __floats2half2_rn(a, b);
    return *(unsigned*)&h;
}

// ======================================================================
// fp32 -> fp16 conversion (7 arrays in one launch)
// ======================================================================
struct F2HArgs {
    const float2* src[7];
    __half2*      dst[7];
    int           n2[7];   // element pairs
};

__global__ void f2h_kernel(F2HArgs p) {
    const int seg = blockIdx.y;
    const int n2 = p.n2[seg];
    const float2* s = p.src[seg];
    __half2* d = p.dst[seg];
    for (int i = blockIdx.x * blockDim.x + threadIdx.x; i < n2;
         i += gridDim.x * blockDim.x) {
        float2 v = s[i];
        d[i] = __floats2half2_rn(v.x, v.y);
    }
}

// ======================================================================
// GEMM (NT): C[m][n] = (sum_k A[m][k]*W[n][k] + bias[n]) * oscale
// fp16 operands, fp32 accumulate. 128x128 tile, K-slice 32, 256 threads
// (8 warps, warp tile 64x32). cp.async double-buffered smem, ldmatrix
// fragments (row stride 40 halves = 80B -> conflict-free LDSM).
// ======================================================================
#define GST   40
#define GHALF (128 * GST)     // halves per matrix per stage

template<bool OUTH>
__global__ __launch_bounds__(256, 2)
void gemm_h(const __half* __restrict__ A, const __half* __restrict__ W,
            const float* __restrict__ bias, void* __restrict__ Cout, float oscale)
{
    __shared__ __half smh[2][2 * GHALF];

    const int tid  = threadIdx.x;
    const int lane = tid & 31;
    const int warp = tid >> 5;
    const int wm   = (warp >> 2) * 64;
    const int wn   = (warp & 3) * 32;
    const int g    = lane >> 2;
    const int tg   = lane & 3;
    const int m0   = blockIdx.y * 128;
    const int n0   = blockIdx.x * 128;

    // loader mapping: 128 rows x 32 halves (4 chunks of 16B), 2 chunks/thread/matrix
    const int lrow = tid >> 1;
    const int lch  = (tid & 1) * 2;

    // ldsm lane bases
    const int a_r = lane & 15;
    const int a_k = ((lane >> 4) & 1) * 8;
    const int b_n = ((lane >> 4) & 1) * 8 + (lane & 7);
    const int b_k = ((lane >> 3) & 1) * 8;

    float c[4][4][4];
#pragma unroll
    for (int i = 0; i < 4; i++)
#pragma unroll
        for (int j = 0; j < 4; j++)
#pragma unroll
            for (int e = 0; e < 4; e++) c[i][j][e] = 0.0f;

    const __half* Agp = A + (size_t)(m0 + lrow) * D_SZ + lch * 8;
    const __half* Wgp = W + (size_t)(n0 + lrow) * D_SZ + lch * 8;

#define G_ISSUE(s) do {                                                     \
        unsigned sa = sptr(&smh[(s) & 1][0]) + (lrow * GST + lch * 8) * 2;  \
        unsigned sw = sptr(&smh[(s) & 1][GHALF]) + (lrow * GST + lch * 8) * 2; \
        cp16(sa,      Agp + (s) * 32);                                      \
        cp16(sa + 16, Agp + (s) * 32 + 8);                                  \
        cp16(sw,      Wgp + (s) * 32);                                      \
        cp16(sw + 16, Wgp + (s) * 32 + 8);                                  \
        CP_COMMIT;                                                          \
    } while (0)

    G_ISSUE(0);

    const int NSTG = D_SZ / 32;   // 32
    for (int s = 0; s < NSTG; s++) {
        if (s + 1 < NSTG) { G_ISSUE(s + 1); CP_WAIT1; }
        else              { CP_WAIT0; }
        __syncthreads();

        const unsigned Ab = sptr(&smh[s & 1][0]);
        const unsigned Wb = sptr(&smh[s & 1][GHALF]);

#pragma unroll
        for (int ka = 0; ka < 2; ka++) {
            unsigned af[4][4];
#pragma unroll
            for (int ma = 0; ma < 4; ma++)
                ldsm4(af[ma][0], af[ma][1], af[ma][2], af[ma][3],
                      Ab + ((wm + ma * 16 + a_r) * GST + ka * 16 + a_k) * 2);
#pragma unroll
            for (int np = 0; np < 2; np++) {
                unsigned t0, t1, t2, t3;
                ldsm4(t0, t1, t2, t3,
                      Wb + ((wn + np * 16 + b_n) * GST + ka * 16 + b_k) * 2);
#pragma unroll
                for (int ma = 0; ma < 4; ma++) {
                    mma16(c[ma][2 * np],     af[ma], t0, t1);
                    mma16(c[ma][2 * np + 1], af[ma], t2, t3);
                }
            }
        }
        __syncthreads();
    }

    // epilogue
#pragma unroll
    for (int ma = 0; ma < 4; ma++) {
        const int r = m0 + wm + ma * 16 + g;
#pragma unroll
        for (int na = 0; na < 4; na++) {
            const int cc = n0 + wn + na * 8 + 2 * tg;
            const float b0 = bias[cc], b1 = bias[cc + 1];
            if (OUTH) {
                __half2* O = (__half2*)Cout;
                O[((size_t)r * D_SZ + cc) >> 1] =
                    __floats2half2_rn((c[ma][na][0] + b0) * oscale,
                                      (c[ma][na][1] + b1) * oscale);
                O[((size_t)(r + 8) * D_SZ + cc) >> 1] =
                    __floats2half2_rn((c[ma][na][2] + b0) * oscale,
                                      (c[ma][na][3] + b1) * oscale);
            } else {
                float* O = (float*)Cout;
                *(float2*)&O[(size_t)r * D_SZ + cc] =
                    make_float2(c[ma][na][0] + b0, c[ma][na][1] + b1);
                *(float2*)&O[(size_t)(r + 8) * D_SZ + cc] =
                    make_float2(c[ma][na][2] + b0, c[ma][na][3] + b1);
            }
        }
    }
}

// ======================================================================
// Flash attention, fp16 mma m16n8k16, fp32 accum/softmax.
// Grid (B*H, L/64), 128 threads (4 warps, 16 q-rows each).
// P tile never touches smem: C-frag (cols 2tg,2tg+1) == A-frag layout
// after half2 packing. K/V tiles double-buffered via cp.async; fragment
// loads via ldmatrix (row stride 72 halves = 144B -> conflict-free).
// Q arrives pre-scaled by 1/8 (projection epilogue).
// ======================================================================
#define AST   72
#define AHALF (64 * AST)      // halves per matrix per stage

__global__ __launch_bounds__(128)
void attn_h(const __half* __restrict__ qp, const __half* __restrict__ kp,
            const __half* __restrict__ vp, __half* __restrict__ ctx)
{
    __shared__ __half smh[2][2 * AHALF];   // [stage][K | V]

    const int tid  = threadIdx.x;
    const int lane = tid & 31;
    const int warp = tid >> 5;
    const int g    = lane >> 2;
    const int tg   = lane & 3;

    const int bh = blockIdx.x;
    const int b  = bh >> 4;
    const int h  = bh & 15;
    const int q0 = blockIdx.y * 64;
    const int head = h * DH;

    const int r1 = warp * 16 + g;

    // ldsm lane bases
    const int kb_n = ((lane >> 4) & 1) * 8 + (lane & 7);
    const int kb_k = ((lane >> 3) & 1) * 8;
    const int vb_j = ((lane >> 3) & 1) * 8 + (lane & 7);
    const int vb_d = ((lane >> 4) & 1) * 8;

    // loader mapping: 64 rows x 8 chunks(16B), 4 chunks/thread/matrix
    const int lrow = tid >> 1;
    const int lch  = (tid & 1) * 4;

    // ---- Q A-fragments straight from gmem (fp16, pre-scaled) ----
    unsigned qf[4][4];
    {
        const size_t ra = (size_t)(b * L_SZ + q0 + r1) * D_SZ + head;
        const size_t rb = ra + (size_t)8 * D_SZ;
#pragma unroll
        for (int ka = 0; ka < 4; ka++) {
            qf[ka][0] = *(const unsigned*)(qp + ra + ka * 16 + 2 * tg);
            qf[ka][1] = *(const unsigned*)(qp + rb + ka * 16 + 2 * tg);
            qf[ka][2] = *(const unsigned*)(qp + ra + ka * 16 + 8 + 2 * tg);
            qf[ka][3] = *(const unsigned*)(qp + rb + ka * 16 + 8 + 2 * tg);
        }
    }

    float of[8][4];
#pragma unroll
    for (int na = 0; na < 8; na++)
#pragma unroll
        for (int e = 0; e < 4; e++) of[na][e] = 0.0f;

    float m1 = -INFINITY, m2 = -INFINITY, l1 = 0.0f, l2 = 0.0f;

    const __half* kgp = kp + (size_t)(b * L_SZ + lrow) * D_SZ + head + lch * 8;
    const __half* vgp = vp + (size_t)(b * L_SZ + lrow) * D_SZ + head + lch * 8;

#define A_ISSUE(t) do {                                                         \
        const size_t go = (size_t)(t) * 64 * D_SZ;                              \
        unsigned sk = sptr(&smh[(t) & 1][0]) + (lrow * AST + lch * 8) * 2;      \
        unsigned sv = sptr(&smh[(t) & 1][AHALF]) + (lrow * AST + lch * 8) * 2;  \
        cp16(sk,      kgp + go);      cp16(sv,      vgp + go);                  \
        cp16(sk + 16, kgp + go + 8);  cp16(sv + 16, vgp + go + 8);              \
        cp16(sk + 32, kgp + go + 16); cp16(sv + 32, vgp + go + 16);             \
        cp16(sk + 48, kgp + go + 24); cp16(sv + 48, vgp + go + 24);             \
        CP_COMMIT;                                                              \
    } while (0)

    A_ISSUE(0);

    const int NT = L_SZ / 64;   // 32
    for (int kt = 0; kt < NT; kt++) {
        if (kt + 1 < NT) { A_ISSUE(kt + 1); CP_WAIT1; }
        else             { CP_WAIT0; }
        __syncthreads();

        const unsigned Kb = sptr(&smh[kt & 1][0]);
        const unsigned Vb = sptr(&smh[kt & 1][AHALF]);

        // ---- S = Qs @ K^T ----
        float sf[8][4];
#pragma unroll
        for (int na = 0; na < 8; na++)
#pragma unroll
            for (int e = 0; e < 4; e++) sf[na][e] = 0.0f;

#pragma unroll
        for (int ka = 0; ka < 4; ka++) {
#pragma unroll
            for (int np = 0; np < 4; np++) {
                unsigned t0, t1, t2, t3;
                ldsm4(t0, t1, t2, t3,
                      Kb + ((np * 16 + kb_n) * AST + ka * 16 + kb_k) * 2);
                mma16(sf[2 * np],     qf[ka], t0, t1);
                mma16(sf[2 * np + 1], qf[ka], t2, t3);
            }
        }

        // ---- online softmax (register stats, shuffle row-reduce) ----
        float mx1 = -INFINITY, mx2 = -INFINITY;
#pragma unroll
        for (int na = 0; na < 8; na++) {
            mx1 = fmaxf(mx1, fmaxf(sf[na][0], sf[na][1]));
            mx2 = fmaxf(mx2, fmaxf(sf[na][2], sf[na][3]));
        }
        mx1 = fmaxf(mx1, __shfl_xor_sync(0xffffffffu, mx1, 1));
        mx1 = fmaxf(mx1, __shfl_xor_sync(0xffffffffu, mx1, 2));
        mx2 = fmaxf(mx2, __shfl_xor_sync(0xffffffffu, mx2, 1));
        mx2 = fmaxf(mx2, __shfl_xor_sync(0xffffffffu, mx2, 2));

        const float mn1 = fmaxf(m1, mx1);
        const float mn2 = fmaxf(m2, mx2);
        const float fa1 = __expf(m1 - mn1);
        const float fa2 = __expf(m2 - mn2);

        float s1 = 0.0f, s2 = 0.0f;
#pragma unroll
        for (int na = 0; na < 8; na++) {
            sf[na][0] = __expf(sf[na][0] - mn1);
            sf[na][1] = __expf(sf[na][1] - mn1);
            sf[na][2] = __expf(sf[na][2] - mn2);
            sf[na][3] = __expf(sf[na][3] - mn2);
            s1 += sf[na][0] + sf[na][1];
            s2 += sf[na][2] + sf[na][3];
        }
        s1 += __shfl_xor_sync(0xffffffffu, s1, 1);
        s1 += __shfl_xor_sync(0xffffffffu, s1, 2);
        s2 += __shfl_xor_sync(0xffffffffu, s2, 1);
        s2 += __shfl_xor_sync(0xffffffffu, s2, 2);

        l1 = l1 * fa1 + s1;  m1 = mn1;
        l2 = l2 * fa2 + s2;  m2 = mn2;

        // ---- pack P C-frags directly into A-frags (no smem) ----
        // C-frag of S tile na=2ka,2ka+1 covers cols [ka*16, ka*16+16):
        //   a0 = rows r1,    cols 2tg/2tg+1      (from sf[2ka][0..1])
        //   a1 = rows r1+8,  cols 2tg/2tg+1      (from sf[2ka][2..3])
        //   a2 = rows r1,    cols 8+2tg/8+2tg+1  (from sf[2ka+1][0..1])
        //   a3 = rows r1+8,  cols 8+2tg/8+2tg+1  (from sf[2ka+1][2..3])
        unsigned pf[4][4];
#pragma unroll
        for (int ka = 0; ka < 4; ka++) {
            pf[ka][0] = pack_h2(sf[2*ka][0],     sf[2*ka][1]);
            pf[ka][1] = pack_h2(sf[2*ka][2],     sf[2*ka][3]);
            pf[ka][2] = pack_h2(sf[2*ka+1][0],   sf[2*ka+1][1]);
            pf[ka][3] = pack_h2(sf[2*ka+1][2],   sf[2*ka+1][3]);
        }

#pragma unroll
        for (int na = 0; na < 8; na++) {
            of[na][0] *= fa1; of[na][1] *= fa1;
            of[na][2] *= fa2; of[na][3] *= fa2;
        }

        // ---- O += P @ V ----
#pragma unroll
        for (int ka = 0; ka < 4; ka++) {
#pragma unroll
            for (int dp = 0; dp < 4; dp++) {
                unsigned t0, t1, t2, t3;
                ldsm4t(t0, t1, t2, t3,
                       Vb + ((ka * 16 + vb_j) * AST + dp * 16 + vb_d) * 2);
                mma16(of[2 * dp],     pf[ka], t0, t1);
                mma16(of[2 * dp + 1], pf[ka], t2, t3);
            }
        }
        __syncthreads();
    }

    // ---- normalize + write (fp16 ctx) ----
    const float inv1 = 1.0f / l1;
    const float inv2 = 1.0f / l2;
    __half2* o1 = (__half2*)(ctx + (size_t)(b * L_SZ + q0 + r1) * D_SZ + head);
    __half2* o2 = (__half2*)(ctx + (size_t)(b * L_SZ + q0 + r1 + 8) * D_SZ + head);
#pragma unroll
    for (int na = 0; na < 8; na++) {
        const int cp = (na * 8 + 2 * tg) >> 1;
        o1[cp] = __floats2half2_rn(of[na][0] * inv1, of[na][1] * inv1);
        o2[cp] = __floats2half2_rn(of[na][2] * inv2, of[na][3] * inv2);
    }
}

// ======================================================================
// Launch
// ======================================================================
extern "C" void kernel_launch(void* const* d_in, const int* in_sizes, int n_in,
                              void* d_out, int out_size)
{
    const float* q   = (const float*)d_in[0];
    const float* k   = (const float*)d_in[1];
    const float* v   = (const float*)d_in[2];
    const float* w_q = (const float*)d_in[3];
    const float* b_q = (const float*)d_in[4];
    const float* w_k = (const float*)d_in[5];
    const float* b_k = (const float*)d_in[6];
    const float* w_v = (const float*)d_in[7];
    const float* b_v = (const float*)d_in[8];
    const float* w_o = (const float*)d_in[9];
    const float* b_o = (const float*)d_in[10];
    float* out = (float*)d_out;

    __half *qh, *kh, *vh, *wqh, *wkh, *wvh, *woh, *qpd, *kpd, *vpd, *ctxd;
    cudaGetSymbolAddress((void**)&qh,  g_qh);
    cudaGetSymbolAddress((void**)&kh,  g_kh);
    cudaGetSymbolAddress((void**)&vh,  g_vh);
    cudaGetSymbolAddress((void**)&wqh, g_wqh);
    cudaGetSymbolAddress((void**)&wkh, g_wkh);
    cudaGetSymbolAddress((void**)&wvh, g_wvh);
    cudaGetSymbolAddress((void**)&woh, g_woh);
    cudaGetSymbolAddress((void**)&qpd, g_qp);
    cudaGetSymbolAddress((void**)&kpd, g_kp);
    cudaGetSymbolAddress((void**)&vpd, g_vp);
    cudaGetSymbolAddress((void**)&ctxd, g_ctx);

    // 1) convert inputs + weights to fp16
    F2HArgs fa;
    fa.src[0] = (const float2*)q;   fa.dst[0] = (__half2*)qh;  fa.n2[0] = M_SZ * D_SZ / 2;
    fa.src[1] = (const float2*)k;   fa.dst[1] = (__half2*)kh;  fa.n2[1] = M_SZ * D_SZ / 2;
    fa.src[2] = (const float2*)v;   fa.dst[2] = (__half2*)vh;  fa.n2[2] = M_SZ * D_SZ / 2;
    fa.src[3] = (const float2*)w_q; fa.dst[3] = (__half2*)wqh; fa.n2[3] = D_SZ * D_SZ / 2;
    fa.src[4] = (const float2*)w_k; fa.dst[4] = (__half2*)wkh; fa.n2[4] = D_SZ * D_SZ / 2;
    fa.src[5] = (const float2*)w_v; fa.dst[5] = (__half2*)wvh; fa.n2[5] = D_SZ * D_SZ / 2;
    fa.src[6] = (const float2*)w_o; fa.dst[6] = (__half2*)woh; fa.n2[6] = D_SZ * D_SZ / 2;
    f2h_kernel<<<dim3(1024, 7), 256>>>(fa);

    // 2) projections (q scaled by 1/sqrt(Dh) in epilogue)
    dim3 gGrid(D_SZ / 128, M_SZ / 128);   // (8, 32)
    gemm_h<true><<<gGrid, 256>>>(qh, wqh, b_q, qpd, 0.125f);
    gemm_h<true><<<gGrid, 256>>>(kh, wkh, b_k, kpd, 1.0f);
    gemm_h<true><<<gGrid, 256>>>(vh, wvh, b_v, vpd, 1.0f);

    // 3) attention
    attn_h<<<dim3(B_SZ * H_SZ, L_SZ / 64), 128>>>(qpd, kpd, vpd, ctxd);

    // 4) output projection (fp32 out)
    gemm_h<false><<<gGrid, 256>>>(ctxd, woh, b_o, out, 1.0f);
}

// round 5
// speedup vs baseline: 5.3730x; 1.0179x over previous
#include <cuda_runtime.h>
#include <cuda_fp16.h>
#include <math.h>

#define B_SZ   2
#define L_SZ   2048
#define D_SZ   1024
#define H_SZ   16
#define DH     64
#define M_SZ   (B_SZ * L_SZ)   // 4096

// ---------------- scratch (device globals) ----------------
__device__ __half g_qh[M_SZ * D_SZ];
__device__ __half g_kh[M_SZ * D_SZ];
__device__ __half g_vh[M_SZ * D_SZ];
__device__ __half g_wqh[D_SZ * D_SZ];
__device__ __half g_wkh[D_SZ * D_SZ];
__device__ __half g_wvh[D_SZ * D_SZ];
__device__ __half g_woh[D_SZ * D_SZ];
__device__ __half g_qp[M_SZ * D_SZ];
__device__ __half g_kp[M_SZ * D_SZ];
__device__ __half g_vp[M_SZ * D_SZ];
__device__ __half g_ctx[M_SZ * D_SZ];

// ---------------- PTX helpers ----------------
__device__ __forceinline__ unsigned sptr(const void* p) {
    return (unsigned)__cvta_generic_to_shared(p);
}
__device__ __forceinline__ void ldsm4(unsigned& a, unsigned& b, unsigned& c, unsigned& d,
                                      unsigned addr) {
    asm volatile("ldmatrix.sync.aligned.m8n8.x4.shared.b16 {%0,%1,%2,%3}, [%4];"
                 : "=r"(a), "=r"(b), "=r"(c), "=r"(d) : "r"(addr));
}
__device__ __forceinline__ void ldsm4t(unsigned& a, unsigned& b, unsigned& c, unsigned& d,
                                       unsigned addr) {
    asm volatile("ldmatrix.sync.aligned.m8n8.x4.trans.shared.b16 {%0,%1,%2,%3}, [%4];"
                 : "=r"(a), "=r"(b), "=r"(c), "=r"(d) : "r"(addr));
}
__device__ __forceinline__ void mma16(float* c, const unsigned* a, unsigned b0, unsigned b1) {
    asm volatile(
        "mma.sync.aligned.m16n8k16.row.col.f32.f16.f16.f32 "
        "{%0,%1,%2,%3}, {%4,%5,%6,%7}, {%8,%9}, {%0,%1,%2,%3};"
        : "+f"(c[0]), "+f"(c[1]), "+f"(c[2]), "+f"(c[3])
        : "r"(a[0]), "r"(a[1]), "r"(a[2]), "r"(a[3]), "r"(b0), "r"(b1));
}
__device__ __forceinline__ void cp16(unsigned s, const void* g) {
    asm volatile("cp.async.cg.shared.global [%0], [%1], 16;" :: "r"(s), "l"(g));
}
#define CP_COMMIT asm volatile("cp.async.commit_group;")
#define CP_WAIT1  asm volatile("cp.async.wait_group 1;")

__device__ __forceinline__ unsigned pack_h2(float a, float b) {
    __half2 h = __floats2half2_rn(a, b);
    return *(unsigned*)&h;
}

// ======================================================================
// fp32 -> fp16 conversion (7 arrays in one launch)
// ======================================================================
struct F2HArgs {
    const float2* src[7];
    __half2*      dst[7];
    int           n2[7];
};

__global__ void f2h_kernel(F2HArgs p) {
    const int seg = blockIdx.y;
    const int n2 = p.n2[seg];
    const float2* s = p.src[seg];
    __half2* d = p.dst[seg];
    for (int i = blockIdx.x * blockDim.x + threadIdx.x; i < n2;
         i += gridDim.x * blockDim.x) {
        float2 v = s[i];
        d[i] = __floats2half2_rn(v.x, v.y);
    }
}

// ======================================================================
// Batched GEMM (NT): C[m][n] = (sum_k A[m][k]*W[n][k] + bias[n]) * oscale
// blockIdx.z selects the problem (Q/K/V fused into one launch).
// fp16 operands, fp32 accum. 128x128 tile, BK=64, 3-stage cp.async ring,
// ONE __syncthreads per K-iteration. 256 threads, warp tile 64x32.
// smem row stride 72 halves (144B) -> conflict-free ldmatrix.
// ======================================================================
#define GBK   64
#define GAST  72
#define GMAT  (128 * GAST)                 // halves per matrix per stage
#define GSTG_BYTES (2 * GMAT * 2)          // bytes per stage (A + W)
#define GSM_BYTES  (3 * GSTG_BYTES)        // 110592

struct GemmBatch {
    const __half* A[3];
    const __half* W[3];
    const float*  bias[3];
    void*         out[3];
    float         oscale[3];
};

template<bool OUTH>
__global__ __launch_bounds__(256, 2)
void gemm_h(GemmBatch p)
{
    extern __shared__ __half smg[];

    const int z = blockIdx.z;
    const __half* __restrict__ A = p.A[z];
    const __half* __restrict__ W = p.W[z];
    const float*  __restrict__ bias = p.bias[z];
    const float oscale = p.oscale[z];

    const int tid  = threadIdx.x;
    const int lane = tid & 31;
    const int warp = tid >> 5;
    const int wm   = (warp >> 2) * 64;
    const int wn   = (warp & 3) * 32;
    const int g    = lane >> 2;
    const int tg   = lane & 3;
    const int m0   = blockIdx.y * 128;
    const int n0   = blockIdx.x * 128;

    // loader: 128 rows x 64 halves = 8 chunks(16B)/row; 2 threads/row, 4 chunks each
    const int lrow = tid >> 1;
    const int lch  = (tid & 1) * 4;        // chunk index 0 or 4

    // ldsm lane bases
    const int a_r = lane & 15;
    const int a_k = ((lane >> 4) & 1) * 8;
    const int b_n = ((lane >> 4) & 1) * 8 + (lane & 7);
    const int b_k = ((lane >> 3) & 1) * 8;

    float c[4][4][4];
#pragma unroll
    for (int i = 0; i < 4; i++)
#pragma unroll
        for (int j = 0; j < 4; j++)
#pragma unroll
            for (int e = 0; e < 4; e++) c[i][j][e] = 0.0f;

    const __half* Agp = A + (size_t)(m0 + lrow) * D_SZ + lch * 8;
    const __half* Wgp = W + (size_t)(n0 + lrow) * D_SZ + lch * 8;
    const unsigned smb = sptr(smg);

#define G_ISSUE(s) do {                                                        \
        const unsigned st = ((s) % 3) * GSTG_BYTES;                            \
        unsigned sa = smb + st + (lrow * GAST + lch * 8) * 2;                  \
        unsigned sw = sa + GMAT * 2;                                           \
        const __half* ag = Agp + (s) * GBK;                                    \
        const __half* wg = Wgp + (s) * GBK;                                    \
        cp16(sa,      ag);      cp16(sa + 16, ag + 8);                         \
        cp16(sa + 32, ag + 16); cp16(sa + 48, ag + 24);                        \
        cp16(sw,      wg);      cp16(sw + 16, wg + 8);                         \
        cp16(sw + 32, wg + 16); cp16(sw + 48, wg + 24);                        \
        CP_COMMIT;                                                             \
    } while (0)

    G_ISSUE(0);
    G_ISSUE(1);

    const int NSTG = D_SZ / GBK;   // 16
    for (int s = 0; s < NSTG; s++) {
        CP_WAIT1;            // my stage-s groups done (<=1 pending: s+1)
        __syncthreads();     // everyone's stage s visible; compute s-1 done
        if (s + 2 < NSTG) G_ISSUE(s + 2);   // writes (s+2)%3, freed by sync
        else              CP_COMMIT;        // keep group counting uniform

        const unsigned Ab = smb + (s % 3) * GSTG_BYTES;
        const unsigned Wb = Ab + GMAT * 2;

#pragma unroll
        for (int ka = 0; ka < 4; ka++) {
            unsigned af[4][4];
#pragma unroll
            for (int ma = 0; ma < 4; ma++)
                ldsm4(af[ma][0], af[ma][1], af[ma][2], af[ma][3],
                      Ab + ((wm + ma * 16 + a_r) * GAST + ka * 16 + a_k) * 2);
#pragma unroll
            for (int np = 0; np < 2; np++) {
                unsigned t0, t1, t2, t3;
                ldsm4(t0, t1, t2, t3,
                      Wb + ((wn + np * 16 + b_n) * GAST + ka * 16 + b_k) * 2);
#pragma unroll
                for (int ma = 0; ma < 4; ma++) {
                    mma16(c[ma][2 * np],     af[ma], t0, t1);
                    mma16(c[ma][2 * np + 1], af[ma], t2, t3);
                }
            }
        }
    }

    // epilogue
#pragma unroll
    for (int ma = 0; ma < 4; ma++) {
        const int r = m0 + wm + ma * 16 + g;
#pragma unroll
        for (int na = 0; na < 4; na++) {
            const int cc = n0 + wn + na * 8 + 2 * tg;
            const float b0 = bias[cc], b1 = bias[cc + 1];
            if (OUTH) {
                __half2* O = (__half2*)p.out[z];
                O[((size_t)r * D_SZ + cc) >> 1] =
                    __floats2half2_rn((c[ma][na][0] + b0) * oscale,
                                      (c[ma][na][1] + b1) * oscale);
                O[((size_t)(r + 8) * D_SZ + cc) >> 1] =
                    __floats2half2_rn((c[ma][na][2] + b0) * oscale,
                                      (c[ma][na][3] + b1) * oscale);
            } else {
                float* O = (float*)p.out[z];
                *(float2*)&O[(size_t)r * D_SZ + cc] =
                    make_float2(c[ma][na][0] + b0, c[ma][na][1] + b1);
                *(float2*)&O[(size_t)(r + 8) * D_SZ + cc] =
                    make_float2(c[ma][na][2] + b0, c[ma][na][3] + b1);
            }
        }
    }
}

// ======================================================================
// Flash attention, fp16 mma m16n8k16, fp32 accum/softmax.
// Grid (B*H, L/64), 128 threads (4 warps, 16 q-rows each).
// 3-stage cp.async ring, ONE __syncthreads per KV tile.
// P tile stays in registers (C-frag -> A-frag identity after half2 pack).
// ======================================================================
#define AST   72
#define AMAT  (64 * AST)                   // halves per matrix per stage
#define ASTG_BYTES (2 * AMAT * 2)          // bytes per stage (K + V)
#define ASM_BYTES  (3 * ASTG_BYTES)        // 55296

__global__ __launch_bounds__(128)
void attn_h(const __half* __restrict__ qp, const __half* __restrict__ kp,
            const __half* __restrict__ vp, __half* __restrict__ ctx)
{
    extern __shared__ __half sma[];

    const int tid  = threadIdx.x;
    const int lane = tid & 31;
    const int warp = tid >> 5;
    const int g    = lane >> 2;
    const int tg   = lane & 3;

    const int bh = blockIdx.x;
    const int b  = bh >> 4;
    const int h  = bh & 15;
    const int q0 = blockIdx.y * 64;
    const int head = h * DH;

    const int r1 = warp * 16 + g;

    const int kb_n = ((lane >> 4) & 1) * 8 + (lane & 7);
    const int kb_k = ((lane >> 3) & 1) * 8;
    const int vb_j = ((lane >> 3) & 1) * 8 + (lane & 7);
    const int vb_d = ((lane >> 4) & 1) * 8;

    // loader: 64 rows x 64 halves; tid>>1 = row, 4 chunks(16B)/thread/matrix
    const int lrow = tid >> 1;
    const int lch  = (tid & 1) * 4;

    // ---- Q A-fragments straight from gmem (fp16, pre-scaled by 1/8) ----
    unsigned qf[4][4];
    {
        const size_t ra = (size_t)(b * L_SZ + q0 + r1) * D_SZ + head;
        const size_t rb = ra + (size_t)8 * D_SZ;
#pragma unroll
        for (int ka = 0; ka < 4; ka++) {
            qf[ka][0] = *(const unsigned*)(qp + ra + ka * 16 + 2 * tg);
            qf[ka][1] = *(const unsigned*)(qp + rb + ka * 16 + 2 * tg);
            qf[ka][2] = *(const unsigned*)(qp + ra + ka * 16 + 8 + 2 * tg);
            qf[ka][3] = *(const unsigned*)(qp + rb + ka * 16 + 8 + 2 * tg);
        }
    }

    float of[8][4];
#pragma unroll
    for (int na = 0; na < 8; na++)
#pragma unroll
        for (int e = 0; e < 4; e++) of[na][e] = 0.0f;

    float m1 = -INFINITY, m2 = -INFINITY, l1 = 0.0f, l2 = 0.0f;

    const __half* kgp = kp + (size_t)(b * L_SZ + lrow) * D_SZ + head + lch * 8;
    const __half* vgp = vp + (size_t)(b * L_SZ + lrow) * D_SZ + head + lch * 8;
    const unsigned smb = sptr(sma);

#define A_ISSUE(t) do {                                                        \
        const unsigned st = ((t) % 3) * ASTG_BYTES;                            \
        const size_t go = (size_t)(t) * 64 * D_SZ;                             \
        unsigned sk = smb + st + (lrow * AST + lch * 8) * 2;                   \
        unsigned sv = sk + AMAT * 2;                                           \
        cp16(sk,      kgp + go);      cp16(sv,      vgp + go);                 \
        cp16(sk + 16, kgp + go + 8);  cp16(sv + 16, vgp + go + 8);             \
        cp16(sk + 32, kgp + go + 16); cp16(sv + 32, vgp + go + 16);            \
        cp16(sk + 48, kgp + go + 24); cp16(sv + 48, vgp + go + 24);            \
        CP_COMMIT;                                                             \
    } while (0)

    A_ISSUE(0);
    A_ISSUE(1);

    const int NT = L_SZ / 64;   // 32
    for (int kt = 0; kt < NT; kt++) {
        CP_WAIT1;
        __syncthreads();
        if (kt + 2 < NT) A_ISSUE(kt + 2);
        else             CP_COMMIT;

        const unsigned Kb = smb + (kt % 3) * ASTG_BYTES;
        const unsigned Vb = Kb + AMAT * 2;

        // ---- S = Qs @ K^T ----
        float sf[8][4];
#pragma unroll
        for (int na = 0; na < 8; na++)
#pragma unroll
            for (int e = 0; e < 4; e++) sf[na][e] = 0.0f;

#pragma unroll
        for (int ka = 0; ka < 4; ka++) {
#pragma unroll
            for (int np = 0; np < 4; np++) {
                unsigned t0, t1, t2, t3;
                ldsm4(t0, t1, t2, t3,
                      Kb + ((np * 16 + kb_n) * AST + ka * 16 + kb_k) * 2);
                mma16(sf[2 * np],     qf[ka], t0, t1);
                mma16(sf[2 * np + 1], qf[ka], t2, t3);
            }
        }

        // ---- online softmax (register stats, shuffle row-reduce) ----
        float mx1 = -INFINITY, mx2 = -INFINITY;
#pragma unroll
        for (int na = 0; na < 8; na++) {
            mx1 = fmaxf(mx1, fmaxf(sf[na][0], sf[na][1]));
            mx2 = fmaxf(mx2, fmaxf(sf[na][2], sf[na][3]));
        }
        mx1 = fmaxf(mx1, __shfl_xor_sync(0xffffffffu, mx1, 1));
        mx1 = fmaxf(mx1, __shfl_xor_sync(0xffffffffu, mx1, 2));
        mx2 = fmaxf(mx2, __shfl_xor_sync(0xffffffffu, mx2, 1));
        mx2 = fmaxf(mx2, __shfl_xor_sync(0xffffffffu, mx2, 2));

        const float mn1 = fmaxf(m1, mx1);
        const float mn2 = fmaxf(m2, mx2);
        const float fa1 = __expf(m1 - mn1);
        const float fa2 = __expf(m2 - mn2);

        float s1 = 0.0f, s2 = 0.0f;
#pragma unroll
        for (int na = 0; na < 8; na++) {
            sf[na][0] = __expf(sf[na][0] - mn1);
            sf[na][1] = __expf(sf[na][1] - mn1);
            sf[na][2] = __expf(sf[na][2] - mn2);
            sf[na][3] = __expf(sf[na][3] - mn2);
            s1 += sf[na][0] + sf[na][1];
            s2 += sf[na][2] + sf[na][3];
        }
        s1 += __shfl_xor_sync(0xffffffffu, s1, 1);
        s1 += __shfl_xor_sync(0xffffffffu, s1, 2);
        s2 += __shfl_xor_sync(0xffffffffu, s2, 1);
        s2 += __shfl_xor_sync(0xffffffffu, s2, 2);

        l1 = l1 * fa1 + s1;  m1 = mn1;
        l2 = l2 * fa2 + s2;  m2 = mn2;

        // ---- pack P C-frags directly into A-frags (no smem) ----
        unsigned pf[4][4];
#pragma unroll
        for (int ka = 0; ka < 4; ka++) {
            pf[ka][0] = pack_h2(sf[2*ka][0],   sf[2*ka][1]);
            pf[ka][1] = pack_h2(sf[2*ka][2],   sf[2*ka][3]);
            pf[ka][2] = pack_h2(sf[2*ka+1][0], sf[2*ka+1][1]);
            pf[ka][3] = pack_h2(sf[2*ka+1][2], sf[2*ka+1][3]);
        }

#pragma unroll
        for (int na = 0; na < 8; na++) {
            of[na][0] *= fa1; of[na][1] *= fa1;
            of[na][2] *= fa2; of[na][3] *= fa2;
        }

        // ---- O += P @ V ----
#pragma unroll
        for (int ka = 0; ka < 4; ka++) {
#pragma unroll
            for (int dp = 0; dp < 4; dp++) {
                unsigned t0, t1, t2, t3;
                ldsm4t(t0, t1, t2, t3,
                       Vb + ((ka * 16 + vb_j) * AST + dp * 16 + vb_d) * 2);
                mma16(of[2 * dp],     pf[ka], t0, t1);
                mma16(of[2 * dp + 1], pf[ka], t2, t3);
            }
        }
    }

    // ---- normalize + write (fp16 ctx) ----
    const float inv1 = 1.0f / l1;
    const float inv2 = 1.0f / l2;
    __half2* o1 = (__half2*)(ctx + (size_t)(b * L_SZ + q0 + r1) * D_SZ + head);
    __half2* o2 = (__half2*)(ctx + (size_t)(b * L_SZ + q0 + r1 + 8) * D_SZ + head);
#pragma unroll
    for (int na = 0; na < 8; na++) {
        const int cp = (na * 8 + 2 * tg) >> 1;
        o1[cp] = __floats2half2_rn(of[na][0] * inv1, of[na][1] * inv1);
        o2[cp] = __floats2half2_rn(of[na][2] * inv2, of[na][3] * inv2);
    }
}

// ======================================================================
// Launch
// ======================================================================
extern "C" void kernel_launch(void* const* d_in, const int* in_sizes, int n_in,
                              void* d_out, int out_size)
{
    const float* q   = (const float*)d_in[0];
    const float* k   = (const float*)d_in[1];
    const float* v   = (const float*)d_in[2];
    const float* w_q = (const float*)d_in[3];
    const float* b_q = (const float*)d_in[4];
    const float* w_k = (const float*)d_in[5];
    const float* b_k = (const float*)d_in[6];
    const float* w_v = (const float*)d_in[7];
    const float* b_v = (const float*)d_in[8];
    const float* w_o = (const float*)d_in[9];
    const float* b_o = (const float*)d_in[10];
    float* out = (float*)d_out;

    __half *qh, *kh, *vh, *wqh, *wkh, *wvh, *woh, *qpd, *kpd, *vpd, *ctxd;
    cudaGetSymbolAddress((void**)&qh,  g_qh);
    cudaGetSymbolAddress((void**)&kh,  g_kh);
    cudaGetSymbolAddress((void**)&vh,  g_vh);
    cudaGetSymbolAddress((void**)&wqh, g_wqh);
    cudaGetSymbolAddress((void**)&wkh, g_wkh);
    cudaGetSymbolAddress((void**)&wvh, g_wvh);
    cudaGetSymbolAddress((void**)&woh, g_woh);
    cudaGetSymbolAddress((void**)&qpd, g_qp);
    cudaGetSymbolAddress((void**)&kpd, g_kp);
    cudaGetSymbolAddress((void**)&vpd, g_vp);
    cudaGetSymbolAddress((void**)&ctxd, g_ctx);

    cudaFuncSetAttribute(gemm_h<true>,
                         cudaFuncAttributeMaxDynamicSharedMemorySize, GSM_BYTES);
    cudaFuncSetAttribute(gemm_h<false>,
                         cudaFuncAttributeMaxDynamicSharedMemorySize, GSM_BYTES);
    cudaFuncSetAttribute(attn_h,
                         cudaFuncAttributeMaxDynamicSharedMemorySize, ASM_BYTES);

    // 1) convert inputs + weights to fp16
    F2HArgs fa;
    fa.src[0] = (const float2*)q;   fa.dst[0] = (__half2*)qh;  fa.n2[0] = M_SZ * D_SZ / 2;
    fa.src[1] = (const float2*)k;   fa.dst[1] = (__half2*)kh;  fa.n2[1] = M_SZ * D_SZ / 2;
    fa.src[2] = (const float2*)v;   fa.dst[2] = (__half2*)vh;  fa.n2[2] = M_SZ * D_SZ / 2;
    fa.src[3] = (const float2*)w_q; fa.dst[3] = (__half2*)wqh; fa.n2[3] = D_SZ * D_SZ / 2;
    fa.src[4] = (const float2*)w_k; fa.dst[4] = (__half2*)wkh; fa.n2[4] = D_SZ * D_SZ / 2;
    fa.src[5] = (const float2*)w_v; fa.dst[5] = (__half2*)wvh; fa.n2[5] = D_SZ * D_SZ / 2;
    fa.src[6] = (const float2*)w_o; fa.dst[6] = (__half2*)woh; fa.n2[6] = D_SZ * D_SZ / 2;
    f2h_kernel<<<dim3(512, 7), 256>>>(fa);

    // 2) Q/K/V projections fused into one launch (z selects problem)
    GemmBatch pb;
    pb.A[0] = qh;  pb.W[0] = wqh; pb.bias[0] = b_q; pb.out[0] = qpd; pb.oscale[0] = 0.125f;
    pb.A[1] = kh;  pb.W[1] = wkh; pb.bias[1] = b_k; pb.out[1] = kpd; pb.oscale[1] = 1.0f;
    pb.A[2] = vh;  pb.W[2] = wvh; pb.bias[2] = b_v; pb.out[2] = vpd; pb.oscale[2] = 1.0f;
    gemm_h<true><<<dim3(8, 32, 3), 256, GSM_BYTES>>>(pb);

    // 3) attention
    attn_h<<<dim3(B_SZ * H_SZ, L_SZ / 64), 128, ASM_BYTES>>>(qpd, kpd, vpd, ctxd);

    // 4) output projection (fp32 out)
    GemmBatch po;
    po.A[0] = ctxd; po.W[0] = woh; po.bias[0] = b_o; po.out[0] = out; po.oscale[0] = 1.0f;
    po.A[1] = po.A[0]; po.W[1] = po.W[0]; po.bias[1] = po.bias[0]; po.out[1] = po.out[0]; po.oscale[1] = 1.0f;
    po.A[2] = po.A[0]; po.W[2] = po.W[0]; po.bias[2] = po.bias[0]; po.out[2] = po.out[0]; po.oscale[2] = 1.0f;
    gemm_h<false><<<dim3(8, 32, 1), 256, GSM_BYTES>>>(po);
}